// round 2
// baseline (speedup 1.0000x reference)
#include <cuda_runtime.h>

#define NN 50000
#define F 128
#define DEG 16

// Scratch (static device allocations are the sanctioned workaround)
__device__ float g_A[(size_t)NN * F];   // x @ Wm_top
__device__ float g_B[(size_t)NN * F];   // x @ Wm_bot
__device__ float g_xn[(size_t)NN * F];  // x + agg
__device__ float g_g[(size_t)NN * F];   // segment_sum(adj * x_new[src])

// ---------------------------------------------------------------------------
// C[M,128] = X[M,128] @ W[128,128] (+bias). Register-tiled fp32 GEMM.
// Block = 256 threads: 32 col-groups (4 cols each) x 8 row-groups (8 rows each)
// BM=64. Xs broadcast reads are conflict-free (whole warp shares one row-group).
// ---------------------------------------------------------------------------
__global__ __launch_bounds__(256) void gemm128_k(
    const float* __restrict__ X, const float* __restrict__ W,
    const float* __restrict__ bias, float* __restrict__ C, int M)
{
    __shared__ float Xs[64][128];  // 32 KB
    const int tid  = threadIdx.x;
    const int c4   = (tid & 31) << 2;   // column base (0..124)
    const int r8   = (tid >> 5) << 3;   // row base within tile (0..56)
    const int row0 = blockIdx.x * 64;

    // Cooperative load of the 64x128 X tile (8 float4 per thread, coalesced)
    {
        const float4* Xv  = (const float4*)X;
        float4*       Xsv = (float4*)&Xs[0][0];
#pragma unroll
        for (int i = 0; i < 8; i++) {
            int idx = tid + i * 256;     // float4 index within tile
            int r   = idx >> 5;
            int col = idx & 31;
            float4 v = make_float4(0.f, 0.f, 0.f, 0.f);
            if (row0 + r < M) v = Xv[(size_t)(row0 + r) * 32 + col];
            Xsv[idx] = v;
        }
    }
    __syncthreads();

    float acc[8][4];
#pragma unroll
    for (int i = 0; i < 8; i++)
#pragma unroll
        for (int j = 0; j < 4; j++) acc[i][j] = 0.f;

#pragma unroll 8
    for (int k = 0; k < 128; k++) {
        const float4 w = *(const float4*)(W + k * 128 + c4);  // L1-resident
#pragma unroll
        for (int i = 0; i < 8; i++) {
            const float xv = Xs[r8 + i][k];  // warp-broadcast
            acc[i][0] = fmaf(xv, w.x, acc[i][0]);
            acc[i][1] = fmaf(xv, w.y, acc[i][1]);
            acc[i][2] = fmaf(xv, w.z, acc[i][2]);
            acc[i][3] = fmaf(xv, w.w, acc[i][3]);
        }
    }

    float4 bv = make_float4(0.f, 0.f, 0.f, 0.f);
    if (bias) bv = *(const float4*)(bias + c4);
#pragma unroll
    for (int i = 0; i < 8; i++) {
        int r = row0 + r8 + i;
        if (r < M) {
            float4 o;
            o.x = acc[i][0] + bv.x;
            o.y = acc[i][1] + bv.y;
            o.z = acc[i][2] + bv.z;
            o.w = acc[i][3] + bv.w;
            *(float4*)(C + (size_t)r * 128 + c4) = o;
        }
    }
}

__device__ __forceinline__ float sigmoidf_(float v) {
    return 1.f / (1.f + __expf(-v));
}

// ---------------------------------------------------------------------------
// Warp per node: x_new[c] = x[c] + sum_e sigmoid(A[c]+B[s_e]) * x[s_e]
// Each lane owns one float4 chunk (128 floats = 32 float4 per row).
// Edge src ids distributed via shfl (lanes 0..15 hold the 16 edges).
// ---------------------------------------------------------------------------
__global__ __launch_bounds__(256) void edge_agg_k(
    const float* __restrict__ x, const int* __restrict__ esrc)
{
    const int gw   = (blockIdx.x * 256 + threadIdx.x) >> 5;
    const int lane = threadIdx.x & 31;
    if (gw >= NN) return;
    const int c    = gw;
    const int s_my = esrc[c * DEG + (lane & 15)];

    const float4* Bv  = (const float4*)g_B;
    const float4* xv4 = (const float4*)x;
    const float4  a   = ((const float4*)g_A)[(size_t)c * 32 + lane];
    float4 acc = make_float4(0.f, 0.f, 0.f, 0.f);

#pragma unroll
    for (int e = 0; e < DEG; e++) {
        const int    s  = __shfl_sync(0xffffffffu, s_my, e);
        const float4 b  = Bv[(size_t)s * 32 + lane];
        const float4 xs = xv4[(size_t)s * 32 + lane];
        acc.x = fmaf(sigmoidf_(a.x + b.x), xs.x, acc.x);
        acc.y = fmaf(sigmoidf_(a.y + b.y), xs.y, acc.y);
        acc.z = fmaf(sigmoidf_(a.z + b.z), xs.z, acc.z);
        acc.w = fmaf(sigmoidf_(a.w + b.w), xs.w, acc.w);
    }

    const float4 xc = xv4[(size_t)c * 32 + lane];
    float4 o = make_float4(xc.x + acc.x, xc.y + acc.y, xc.z + acc.z, xc.w + acc.w);
    ((float4*)g_xn)[(size_t)c * 32 + lane] = o;
}

// ---------------------------------------------------------------------------
// Warp per node: g[c] = sum_e adj[e] * x_new[s_e]
// ---------------------------------------------------------------------------
__global__ __launch_bounds__(256) void gather_k(
    const float* __restrict__ adj, const int* __restrict__ esrc)
{
    const int gw   = (blockIdx.x * 256 + threadIdx.x) >> 5;
    const int lane = threadIdx.x & 31;
    if (gw >= NN) return;
    const int   c    = gw;
    const int   s_my = esrc[c * DEG + (lane & 15)];
    const float a_my = adj[c * DEG + (lane & 15)];

    const float4* xnv = (const float4*)g_xn;
    float4 acc = make_float4(0.f, 0.f, 0.f, 0.f);

#pragma unroll
    for (int e = 0; e < DEG; e++) {
        const int    s  = __shfl_sync(0xffffffffu, s_my, e);
        const float  av = __shfl_sync(0xffffffffu, a_my, e);
        const float4 v  = xnv[(size_t)s * 32 + lane];
        acc.x = fmaf(av, v.x, acc.x);
        acc.y = fmaf(av, v.y, acc.y);
        acc.z = fmaf(av, v.z, acc.z);
        acc.w = fmaf(av, v.w, acc.w);
    }
    ((float4*)g_g)[(size_t)c * 32 + lane] = acc;
}

// ---------------------------------------------------------------------------
extern "C" void kernel_launch(void* const* d_in, const int* in_sizes, int n_in,
                              void* d_out, int out_size)
{
    const float* x      = (const float*)d_in[0];  // [N,128]
    const float* weight = (const float*)d_in[1];  // [128,128]
    const float* bias   = (const float*)d_in[2];  // [128]
    const float* wm     = (const float*)d_in[3];  // [256,128]
    const float* adj    = (const float*)d_in[4];  // [E]
    const int*   esrc   = (const int*)d_in[5];    // [E]
    // d_in[6] edge_dst is implicit (repeat(arange(N), DEG)) — unused
    float* out = (float*)d_out;

    void *pA, *pB, *pxn, *pg;
    cudaGetSymbolAddress(&pA,  g_A);
    cudaGetSymbolAddress(&pB,  g_B);
    cudaGetSymbolAddress(&pxn, g_xn);
    cudaGetSymbolAddress(&pg,  g_g);

    const int gemm_grid = (NN + 63) / 64;   // 782
    const int warp_grid = (NN + 7) / 8;     // 6250 (8 warps/block)

    // A = x @ Wm[0:128],  B = x @ Wm[128:256]
    gemm128_k<<<gemm_grid, 256>>>(x, wm,             nullptr, (float*)pA, NN);
    gemm128_k<<<gemm_grid, 256>>>(x, wm + 128 * 128, nullptr, (float*)pB, NN);

    // x_new = x + sum_e sigmoid(A[c]+B[s]) * x[s]
    edge_agg_k<<<warp_grid, 256>>>(x, esrc);

    // g[c] = sum_e adj[e] * x_new[s]
    gather_k<<<warp_grid, 256>>>(adj, esrc);

    // out = g @ weight + bias   (linearity: commutes with the segment sum)
    gemm128_k<<<gemm_grid, 256>>>((const float*)pg, weight, bias, out, NN);
}